// round 16
// baseline (speedup 1.0000x reference)
#include <cuda_runtime.h>
#include <cuda_fp16.h>
#include <cstdint>
#include <cstddef>
#include <math.h>

// Problem constants
#define BSZ 64
#define LEN 512
#define DIM 1024
#define NH  16
#define DKH 64

#define M_KV 32768
#define OUT_MAIN_ELEMS ((size_t)BSZ*LEN*DIM)

// ---------------------------------------------------------------------------
// scratch (__device__ globals)
// ---------------------------------------------------------------------------
__device__ __half g_v_hi[(size_t)M_KV * 3072];
__device__ __half g_wv_hi[1024 * 3072];
__device__ __half g_wo_hi[1024 * 1024];
__device__ __half g_c_hi[(size_t)M_KV * DIM];
__device__ float g_qp_part[(size_t)32 * BSZ * DIM];
__device__ float g_qp[(size_t)BSZ * DIM];
__device__ float g_w[(size_t)BSZ * NH * 2048];
__device__ float g_cbh[BSZ * NH];
__device__ float g_scores[(size_t)BSZ * NH * LEN];
__device__ float g_back[(size_t)BSZ * NH * LEN];

// ---------------------------------------------------------------------------
// PTX helpers
// ---------------------------------------------------------------------------
__device__ __forceinline__ uint32_t smem_u32(const void* p) {
    uint32_t a;
    asm("{ .reg .u64 t; cvta.to.shared.u64 t, %1; cvt.u32.u64 %0, t; }" : "=r"(a) : "l"(p));
    return a;
}
__device__ __forceinline__ void cpa16(uint32_t s, const void* g) {
    asm volatile("cp.async.cg.shared.global [%0], [%1], 16;" :: "r"(s), "l"(g));
}
__device__ __forceinline__ void cp_commit() {
    asm volatile("cp.async.commit_group;");
}
template<int N> __device__ __forceinline__ void cp_wait() {
    asm volatile("cp.async.wait_group %0;" :: "n"(N));
}
__device__ __forceinline__ void ldsm4(uint32_t* r, uint32_t a) {
    asm volatile("ldmatrix.sync.aligned.m8n8.x4.shared.b16 {%0,%1,%2,%3}, [%4];"
                 : "=r"(r[0]), "=r"(r[1]), "=r"(r[2]), "=r"(r[3]) : "r"(a));
}
__device__ __forceinline__ void mma_f16(float* d, const uint32_t* a, uint32_t b0, uint32_t b1) {
    asm volatile(
        "mma.sync.aligned.m16n8k16.row.col.f32.f16.f16.f32 "
        "{%0,%1,%2,%3}, {%4,%5,%6,%7}, {%8,%9}, {%0,%1,%2,%3};"
        : "+f"(d[0]), "+f"(d[1]), "+f"(d[2]), "+f"(d[3])
        : "r"(a[0]), "r"(a[1]), "r"(a[2]), "r"(a[3]), "r"(b0), "r"(b1));
}

// ---------------------------------------------------------------------------
// fp32 -> fp16 conversion (hi only), 4-way ILP
// ---------------------------------------------------------------------------
struct hf4 { __half a, b, c, d; };

__global__ void split_kernel(const float4* __restrict__ src,
                             __half* __restrict__ hi, size_t n4) {
    const size_t base = (size_t)blockIdx.x * blockDim.x * 4 + threadIdx.x;
    float4 v[4];
    bool ok[4];
    #pragma unroll
    for (int u = 0; u < 4; u++) {
        const size_t i = base + (size_t)u * blockDim.x;
        ok[u] = i < n4;
        if (ok[u]) v[u] = src[i];
    }
    #pragma unroll
    for (int u = 0; u < 4; u++) {
        if (ok[u]) {
            const size_t i = base + (size_t)u * blockDim.x;
            hf4 H = {__float2half_rn(v[u].x), __float2half_rn(v[u].y),
                     __float2half_rn(v[u].z), __float2half_rn(v[u].w)};
            *(hf4*)(hi + i * 4) = H;
        }
    }
}

// ============================================================================
// gate kernel: c_hi[row][n] *= back[b, n>>6, l]   (row = b*512+l)
// grid = 32768 blocks (one row each), 256 thr, 4 halves per thread.
// ============================================================================
__global__ __launch_bounds__(256)
void gate_kernel(__half* __restrict__ c, const float* __restrict__ back)
{
    const int row = blockIdx.x;
    const int t   = threadIdx.x;
    const int b   = row >> 9;
    const int l   = row & 511;
    const int h   = t >> 4;                 // head for columns 4t..4t+3
    const float g = back[((size_t)b * NH + h) * LEN + l];

    __half2* p = (__half2*)(c + (size_t)row * DIM + t * 4);
    __half2 v0 = p[0], v1 = p[1];
    float2 f0 = __half22float2(v0);
    float2 f1 = __half22float2(v1);
    f0.x *= g; f0.y *= g; f1.x *= g; f1.y *= g;
    p[0] = __float22half2_rn(f0);
    p[1] = __float22half2_rn(f1);
}

// ============================================================================
// qp partials: part[kc][b][j] = sum_{k in chunk kc} q[b][k] * Wq[j][k]
// ============================================================================
__global__ __launch_bounds__(256)
void qp_part_kernel(const float* __restrict__ q, const float* __restrict__ Wq,
                    float* __restrict__ part)
{
    __shared__ float q_s[64][65];
    __shared__ float w_s[128][65];
    const int t  = threadIdx.x;
    const int jc = blockIdx.x;
    const int kc = blockIdx.y;
    const int k0 = kc * 64;

    #pragma unroll
    for (int p = 0; p < 4; p++) {
        const int f = t + p * 256;
        const int b = f >> 4, c4 = (f & 15) * 4;
        const float4 v = *(const float4*)(q + (size_t)b * 2048 + k0 + c4);
        q_s[b][c4+0] = v.x; q_s[b][c4+1] = v.y; q_s[b][c4+2] = v.z; q_s[b][c4+3] = v.w;
    }
    #pragma unroll
    for (int p = 0; p < 8; p++) {
        const int f = t + p * 256;
        const int j = f >> 4, c4 = (f & 15) * 4;
        const float4 v = *(const float4*)(Wq + (size_t)(jc * 128 + j) * 2048 + k0 + c4);
        w_s[j][c4+0] = v.x; w_s[j][c4+1] = v.y; w_s[j][c4+2] = v.z; w_s[j][c4+3] = v.w;
    }
    __syncthreads();

    const int jj = t & 63;
    const int bg = t >> 6;
    float acc0[16], acc1[16];
    #pragma unroll
    for (int b = 0; b < 16; b++) { acc0[b] = 0.f; acc1[b] = 0.f; }

    #pragma unroll 4
    for (int kk = 0; kk < 64; kk++) {
        const float w0 = w_s[jj][kk];
        const float w1 = w_s[jj + 64][kk];
        #pragma unroll
        for (int b = 0; b < 16; b++) {
            const float qv = q_s[bg * 16 + b][kk];
            acc0[b] = fmaf(qv, w0, acc0[b]);
            acc1[b] = fmaf(qv, w1, acc1[b]);
        }
    }
    #pragma unroll
    for (int b = 0; b < 16; b++) {
        const size_t base = ((size_t)kc * 64 + bg * 16 + b) * DIM + jc * 128;
        part[base + jj]      = acc0[b];
        part[base + jj + 64] = acc1[b];
    }
}

__global__ __launch_bounds__(256)
void qp_reduce_kernel(const float* __restrict__ part, const float* __restrict__ bq,
                      float* __restrict__ qp)
{
    const int b = blockIdx.x;
    const int t = threadIdx.x;
    #pragma unroll
    for (int jj = 0; jj < 4; jj++) {
        const int j = jj * 256 + t;
        float s = 0.f;
        #pragma unroll 8
        for (int kc = 0; kc < 32; kc++)
            s += part[((size_t)kc * 64 + b) * DIM + j];
        qp[(size_t)b * DIM + j] = s + bq[j];
    }
}

// ============================================================================
// w[b][h][c] = sum_d qp[b][h*64+d] * Wq[h*64+d][c];  cbh[b][h] = qp[b,h,:].bq
// ============================================================================
__global__ __launch_bounds__(256)
void wfold_kernel(const float* __restrict__ qp, const float* __restrict__ Wq,
                  const float* __restrict__ bq,
                  float* __restrict__ w, float* __restrict__ cbh)
{
    __shared__ float qp_s[64][65];
    __shared__ float bq_s[64];
    const int t  = threadIdx.x;
    const int h  = blockIdx.x;
    const int cc = blockIdx.y;

    #pragma unroll
    for (int p = 0; p < 4; p++) {
        const int f = t + p * 256;
        const int b = f >> 4, d4 = (f & 15) * 4;
        const float4 v = *(const float4*)(qp + (size_t)b * DIM + h * 64 + d4);
        qp_s[b][d4+0] = v.x; qp_s[b][d4+1] = v.y; qp_s[b][d4+2] = v.z; qp_s[b][d4+3] = v.w;
    }
    if (t < 16) {
        const float4 v = *(const float4*)(bq + h * 64 + t * 4);
        bq_s[t*4+0] = v.x; bq_s[t*4+1] = v.y; bq_s[t*4+2] = v.z; bq_s[t*4+3] = v.w;
    }
    __syncthreads();

    if (cc == 0 && t < 64) {
        float s = 0.f;
        #pragma unroll 8
        for (int d = 0; d < 64; d++) s = fmaf(qp_s[t][d], bq_s[d], s);
        cbh[t * NH + h] = s;
    }

    const int c = cc * 256 + t;
    float acc[64];
    #pragma unroll
    for (int b = 0; b < 64; b++) acc[b] = 0.f;

    for (int d = 0; d < 64; d++) {
        const float wv = Wq[(size_t)(h * 64 + d) * 2048 + c];
        #pragma unroll
        for (int b = 0; b < 64; b++)
            acc[b] = fmaf(qp_s[b][d], wv, acc[b]);
    }
    #pragma unroll
    for (int b = 0; b < 64; b++)
        w[((size_t)b * NH + h) * 2048 + c] = acc[b];
}

// ============================================================================
// scores[b][h][l] = (k[b,l,:] . w[b,h,:] + cbh[b,h]) / 8
// ============================================================================
#define SC_ROW   68
#define SC_KST   (64 * SC_ROW * 4)
#define SC_WST   (16 * SC_ROW * 4)
#define SC_WOFF  (3 * SC_KST)
#define SC_SMEM  (3 * SC_KST + 3 * SC_WST)

__global__ __launch_bounds__(256)
void scores_kernel(const float* __restrict__ k, const float* __restrict__ w,
                   const float* __restrict__ cbh, float* __restrict__ scores)
{
    extern __shared__ __align__(16) char dsm[];
    const int t  = threadIdx.x;
    const int b  = blockIdx.x;
    const int lc = blockIdx.y;
    const uint32_t sbase = smem_u32(dsm);

    auto issue = [&](int c) {
        const int kc = c * 64;
        const uint32_t kb = sbase + (uint32_t)(c % 3) * SC_KST;
        #pragma unroll
        for (int p = 0; p < 4; p++) {
            const int slot = p * 256 + t;
            const int row = slot >> 4, c4 = (slot & 15) * 4;
            cpa16(kb + (row * SC_ROW + c4) * 4,
                  k + ((size_t)(b * 512 + lc * 64 + row)) * 2048 + kc + c4);
        }
        {
            const int row = t >> 4, c4 = (t & 15) * 4;
            cpa16(sbase + SC_WOFF + (uint32_t)(c % 3) * SC_WST + (row * SC_ROW + c4) * 4,
                  w + ((size_t)(b * NH + row)) * 2048 + kc + c4);
        }
        cp_commit();
    };

    issue(0);
    issue(1);

    const int h  = t & 15;
    const int lg = t >> 4;
    float acc[4] = {0.f, 0.f, 0.f, 0.f};

    for (int c = 0; c < 32; c++) {
        if (c + 1 < 32) cp_wait<1>();
        else            cp_wait<0>();
        __syncthreads();
        if (c + 2 < 32) issue(c + 2);

        const float* ks = (const float*)(dsm + (c % 3) * SC_KST);
        const float* ws = (const float*)(dsm + SC_WOFF + (c % 3) * SC_WST);

        #pragma unroll
        for (int kk4 = 0; kk4 < 16; kk4++) {
            const float4 wv = *(const float4*)&ws[h * SC_ROW + kk4 * 4];
            #pragma unroll
            for (int i = 0; i < 4; i++) {
                const float4 kv = *(const float4*)&ks[(lg * 4 + i) * SC_ROW + kk4 * 4];
                acc[i] = fmaf(kv.x, wv.x, acc[i]);
                acc[i] = fmaf(kv.y, wv.y, acc[i]);
                acc[i] = fmaf(kv.z, wv.z, acc[i]);
                acc[i] = fmaf(kv.w, wv.w, acc[i]);
            }
        }
    }

    const float cv = cbh[b * NH + h];
    #pragma unroll
    for (int i = 0; i < 4; i++) {
        const int l = lc * 64 + lg * 4 + i;
        scores[((size_t)b * NH + h) * LEN + l] = (acc[i] + cv) * 0.125f;
    }
}

// ============================================================================
// qe_score -> back gate (sigmoid) + fcw output
// ============================================================================
__global__ __launch_bounds__(256)
void qe_kernel(const float* __restrict__ qe,
               const float* __restrict__ cw,
               const float* __restrict__ lambdas,
               const float* __restrict__ scores,
               float* __restrict__ back,
               float* __restrict__ fcw)
{
    __shared__ float sc_s[NH][513];
    __shared__ float qe_t[64][33];

    const int b  = blockIdx.x;
    const int i0 = blockIdx.y * 64;
    const int t  = threadIdx.x;

    for (int i = t; i < NH * LEN; i += 256)
        sc_s[i >> 9][i & 511] = scores[(size_t)b * NH * LEN + i];

    const int il = t >> 2;
    const int hg = t & 3;
    float acc[4] = {0.f, 0.f, 0.f, 0.f};

    for (int jc = 0; jc < 16; jc++) {
        __syncthreads();
        #pragma unroll
        for (int p = 0; p < 8; p++) {
            const int f = t + p * 256;
            const int r = f >> 5, c = f & 31;
            qe_t[r][c] = qe[((size_t)b * LEN + i0 + r) * LEN + jc * 32 + c];
        }
        __syncthreads();
        #pragma unroll
        for (int jj = 0; jj < 32; jj++) {
            const float qv = qe_t[il][jj];
            const int j = jc * 32 + jj;
            acc[0] = fmaf(qv, sc_s[hg     ][j], acc[0]);
            acc[1] = fmaf(qv, sc_s[hg + 4 ][j], acc[1]);
            acc[2] = fmaf(qv, sc_s[hg + 8 ][j], acc[2]);
            acc[3] = fmaf(qv, sc_s[hg + 12][j], acc[3]);
        }
    }

    const float c_w = cw[(size_t)b * LEN + i0 + il];
    #pragma unroll
    for (int c = 0; c < 4; c++) {
        const int h = hg + 4 * c;
        const float lam = lambdas[h];
        const float x = acc[c];
        const float z = lam * c_w + (1.f - lam) * x;
        const float bk = 1.f / (1.f + expf(-z));
        back[((size_t)b * NH + h) * LEN + i0 + il] = bk;
        if (h == 0) fcw[(size_t)b * LEN + i0 + il] = x;
    }
}

// ---------------------------------------------------------------------------
// mma.sync fp16 GEMM (R14 config): CTA 128x128, BK=64, 8 warps (4m x 2n),
// 3-stage cp.async, 2 CTA/SM, reg-double-buffered B fragments.
// ---------------------------------------------------------------------------
#define ROW_B    144
#define COMP_B   (128 * ROW_B)           // 18432
#define STAGE_B  (2 * COMP_B)            // 36864
#define GSTAGES  3

template<int OM>
__global__ __launch_bounds__(256, 2)
void gemm_mma(const __half* __restrict__ Ahi,
              const __half* __restrict__ Bhi,
              const float* __restrict__ bias,
              float* __restrict__ Cf, __half* __restrict__ Chi,
              int M, int N, int K)
{
    extern __shared__ __align__(16) char dsm[];
    const int tid  = threadIdx.x;
    const int wid  = tid >> 5;
    const int lane = tid & 31;
    const int wm = wid & 3;
    const int wn = wid >> 2;
    const int n0 = blockIdx.x * 128;
    const int m0 = blockIdx.y * 128;
    const uint32_t sbase = smem_u32(dsm);

    const __half* aH = Ahi + (size_t)m0 * K;
    const __half* bH = Bhi + (size_t)n0 * K;

    float acc[2][8][4];
    #pragma unroll
    for (int a = 0; a < 2; a++)
        #pragma unroll
        for (int b = 0; b < 8; b++)
            #pragma unroll
            for (int c = 0; c < 4; c++) acc[a][b][c] = 0.f;

    const int NC = K >> 6;

    auto issue = [&](int c) {
        const int kc = c << 6;
        const uint32_t sb = sbase + (uint32_t)(c % GSTAGES) * STAGE_B;
        #pragma unroll
        for (int p = 0; p < 4; p++) {
            const int slot = p * 256 + tid;
            const int row = slot >> 3, sg = (slot & 7) * 8;
            cpa16(sb + row * ROW_B + sg * 2, aH + (size_t)row * K + kc + sg);
        }
        #pragma unroll
        for (int p = 0; p < 4; p++) {
            const int slot = p * 256 + tid;
            const int row = slot >> 3, sg = (slot & 7) * 8;
            cpa16(sb + COMP_B + row * ROW_B + sg * 2, bH + (size_t)row * K + kc + sg);
        }
        cp_commit();
    };

    #pragma unroll
    for (int s = 0; s < GSTAGES - 1; s++) issue(s);

    const int arow = wm * 32 + (lane & 15);
    const int acol = (lane >> 4) * 16;
    const int brow = wn * 64 + ((lane >> 4) << 3) + (lane & 7);
    const int bcol = ((lane >> 3) & 1) * 16;

    for (int c = 0; c < NC; c++) {
        if (c + GSTAGES - 2 < NC) cp_wait<GSTAGES - 2>();
        else                      cp_wait<0>();
        __syncthreads();
        if (c + GSTAGES - 1 < NC) issue(c + GSTAGES - 1);

        const uint32_t sb = sbase + (uint32_t)(c % GSTAGES) * STAGE_B;
        const uint32_t abase = sb + arow * ROW_B + acol;
        const uint32_t bbase = sb + COMP_B + brow * ROW_B + bcol;

        uint32_t Bf[2][4][4];
        #pragma unroll
        for (int bt = 0; bt < 4; bt++)
            ldsm4(Bf[0][bt], bbase + bt * 16 * ROW_B);

        #pragma unroll
        for (int ks = 0; ks < 4; ks++) {
            const uint32_t kb = ks * 32;
            uint32_t Af[2][4];
            #pragma unroll
            for (int mt = 0; mt < 2; mt++)
                ldsm4(Af[mt], abase + mt * 16 * ROW_B + kb);
            if (ks < 3) {
                #pragma unroll
                for (int bt = 0; bt < 4; bt++)
                    ldsm4(Bf[(ks + 1) & 1][bt], bbase + bt * 16 * ROW_B + kb + 32);
            }
            const uint32_t (*Bc)[4] = Bf[ks & 1];
            #pragma unroll
            for (int mt = 0; mt < 2; mt++)
                #pragma unroll
                for (int bt = 0; bt < 4; bt++) {
                    mma_f16(acc[mt][2*bt],   Af[mt], Bc[bt][0], Bc[bt][1]);
                    mma_f16(acc[mt][2*bt+1], Af[mt], Bc[bt][2], Bc[bt][3]);
                }
        }
    }

    // ---- epilogue (no gate) ----
    const int tg  = lane >> 2;
    const int tc2 = (lane & 3) * 2;

    #pragma unroll
    for (int mt = 0; mt < 2; mt++) {
        const int r0 = m0 + wm * 32 + mt * 16 + tg;
        const int r1 = r0 + 8;
        #pragma unroll
        for (int nt = 0; nt < 8; nt++) {
            const int cn = n0 + wn * 64 + nt * 8 + tc2;
            const float bs0 = bias[cn], bs1 = bias[cn + 1];
            const float v00 = acc[mt][nt][0] + bs0;
            const float v01 = acc[mt][nt][1] + bs1;
            const float v10 = acc[mt][nt][2] + bs0;
            const float v11 = acc[mt][nt][3] + bs1;
            if (OM == 0) {
                if (r0 < M) *(float2*)&Cf[(size_t)r0 * N + cn] = make_float2(v00, v01);
                if (r1 < M) *(float2*)&Cf[(size_t)r1 * N + cn] = make_float2(v10, v11);
            } else {
                __half2 H0, H1;
                H0.x = __float2half_rn(v00); H0.y = __float2half_rn(v01);
                H1.x = __float2half_rn(v10); H1.y = __float2half_rn(v11);
                if (r0 < M) *(__half2*)(Chi + (size_t)r0 * N + cn) = H0;
                if (r1 < M) *(__half2*)(Chi + (size_t)r1 * N + cn) = H1;
            }
        }
    }
}

// ============================================================================
// launch — GEMM2 runs gate-free so the qp chain overlaps it on a side stream.
// ============================================================================
static inline void launch_split1(cudaStream_t s, const float* src, __half* hi, size_t n) {
    size_t n4 = n / 4;
    int blocks = (int)((n4 + 1023) / 1024);
    split_kernel<<<blocks, 256, 0, s>>>((const float4*)src, hi, n4);
}

extern "C" void kernel_launch(void* const* d_in, const int* in_sizes, int n_in,
                              void* d_out, int out_size)
{
    const float* q   = (const float*)d_in[0];
    const float* k   = (const float*)d_in[1];
    const float* v   = (const float*)d_in[2];
    const float* cw  = (const float*)d_in[3];
    const float* qe  = (const float*)d_in[4];
    const float* Wq  = (const float*)d_in[5];
    const float* bq  = (const float*)d_in[6];
    const float* Wv  = (const float*)d_in[7];
    const float* bv  = (const float*)d_in[8];
    const float* Wo  = (const float*)d_in[9];
    const float* bo  = (const float*)d_in[10];
    const float* lam = (const float*)d_in[11];

    float* out_main = (float*)d_out;
    float* out_fcw  = (float*)d_out + OUT_MAIN_ELEMS;

    __half *v_hi, *wv_hi, *wo_hi, *c_hi;
    float *qpp, *qp, *wvec, *cbh, *scores, *back;
    cudaGetSymbolAddress((void**)&v_hi,  g_v_hi);
    cudaGetSymbolAddress((void**)&wv_hi, g_wv_hi);
    cudaGetSymbolAddress((void**)&wo_hi, g_wo_hi);
    cudaGetSymbolAddress((void**)&c_hi,  g_c_hi);
    cudaGetSymbolAddress((void**)&qpp,   g_qp_part);
    cudaGetSymbolAddress((void**)&qp,    g_qp);
    cudaGetSymbolAddress((void**)&wvec,  g_w);
    cudaGetSymbolAddress((void**)&cbh,   g_cbh);
    cudaGetSymbolAddress((void**)&scores, g_scores);
    cudaGetSymbolAddress((void**)&back,   g_back);

    const int smemg = GSTAGES * STAGE_B;   // 110592
    cudaFuncSetAttribute(gemm_mma<1>, cudaFuncAttributeMaxDynamicSharedMemorySize, smemg);
    cudaFuncSetAttribute(gemm_mma<0>, cudaFuncAttributeMaxDynamicSharedMemorySize, smemg);
    cudaFuncSetAttribute(scores_kernel, cudaFuncAttributeMaxDynamicSharedMemorySize, SC_SMEM);

    // one-time host resources (no device memory; identical work every call)
    static cudaStream_t s_side = nullptr;
    static cudaEvent_t  e_fork = nullptr, e_join = nullptr;
    if (!s_side) {
        cudaStreamCreateWithFlags(&s_side, cudaStreamNonBlocking);
        cudaEventCreateWithFlags(&e_fork, cudaEventDisableTiming);
        cudaEventCreateWithFlags(&e_join, cudaEventDisableTiming);
    }

    // ---- fork: side stream runs the qp chain (overlaps splits + GEMM2) ----
    cudaEventRecord(e_fork, 0);
    cudaStreamWaitEvent(s_side, e_fork, 0);
    qp_part_kernel<<<dim3(8, 32), 256, 0, s_side>>>(q, Wq, qpp);
    qp_reduce_kernel<<<64, 256, 0, s_side>>>(qpp, bq, qp);
    wfold_kernel<<<dim3(16, 8), 256, 0, s_side>>>(qp, Wq, bq, wvec, cbh);
    scores_kernel<<<dim3(BSZ, 8), 256, SC_SMEM, s_side>>>(k, wvec, cbh, scores);
    qe_kernel<<<dim3(BSZ, 8), 256, 0, s_side>>>(qe, cw, lam, scores, back, out_fcw);
    cudaEventRecord(e_join, s_side);

    // ---- main stream: splits then the big ungated GEMM2 ----
    launch_split1(0, v,  v_hi,  (size_t)M_KV * 3072);
    launch_split1(0, Wv, wv_hi, (size_t)1024 * 3072);
    launch_split1(0, Wo, wo_hi, (size_t)1024 * 1024);

    // GEMM2: v @ Wv^T + bv -> concat (fp16 out, UNGATED)
    gemm_mma<1><<<dim3(8, 256), 256, smemg>>>(
        v_hi, wv_hi, bv, nullptr, c_hi, M_KV, DIM, 3 * DIM);

    // ---- join: gate needs `back` from the side stream ----
    cudaStreamWaitEvent(0, e_join, 0);

    // gate pass: c_hi *= back
    gate_kernel<<<M_KV, 256>>>(c_hi, back);

    // GEMM3: concat @ Wo^T + bo -> main output (fp32)
    gemm_mma<0><<<dim3(8, 256), 256, smemg>>>(
        c_hi, wo_hi, bo, out_main, nullptr, M_KV, DIM, DIM);
}

// round 17
// speedup vs baseline: 1.0090x; 1.0090x over previous
#include <cuda_runtime.h>
#include <cuda_fp16.h>
#include <cstdint>
#include <cstddef>
#include <math.h>

// Problem constants
#define BSZ 64
#define LEN 512
#define DIM 1024
#define NH  16
#define DKH 64

#define M_KV 32768
#define OUT_MAIN_ELEMS ((size_t)BSZ*LEN*DIM)

// ---------------------------------------------------------------------------
// scratch (__device__ globals)
// ---------------------------------------------------------------------------
__device__ __half g_v_hi[(size_t)M_KV * 3072];
__device__ __half g_wv_hi[1024 * 3072];
__device__ __half g_wo_hi[1024 * 1024];
__device__ __half g_c_hi[(size_t)M_KV * DIM];
__device__ float g_qp_part[(size_t)32 * BSZ * DIM];
__device__ float g_qp[(size_t)BSZ * DIM];
__device__ float g_w[(size_t)BSZ * NH * 2048];
__device__ float g_cbh[BSZ * NH];
__device__ float g_scores[(size_t)BSZ * NH * LEN];
__device__ float g_back[(size_t)BSZ * NH * LEN];

// ---------------------------------------------------------------------------
// PTX helpers
// ---------------------------------------------------------------------------
__device__ __forceinline__ uint32_t smem_u32(const void* p) {
    uint32_t a;
    asm("{ .reg .u64 t; cvta.to.shared.u64 t, %1; cvt.u32.u64 %0, t; }" : "=r"(a) : "l"(p));
    return a;
}
__device__ __forceinline__ void cpa16(uint32_t s, const void* g) {
    asm volatile("cp.async.cg.shared.global [%0], [%1], 16;" :: "r"(s), "l"(g));
}
__device__ __forceinline__ void cp_commit() {
    asm volatile("cp.async.commit_group;");
}
template<int N> __device__ __forceinline__ void cp_wait() {
    asm volatile("cp.async.wait_group %0;" :: "n"(N));
}
__device__ __forceinline__ void ldsm4(uint32_t* r, uint32_t a) {
    asm volatile("ldmatrix.sync.aligned.m8n8.x4.shared.b16 {%0,%1,%2,%3}, [%4];"
                 : "=r"(r[0]), "=r"(r[1]), "=r"(r[2]), "=r"(r[3]) : "r"(a));
}
__device__ __forceinline__ void mma_f16(float* d, const uint32_t* a, uint32_t b0, uint32_t b1) {
    asm volatile(
        "mma.sync.aligned.m16n8k16.row.col.f32.f16.f16.f32 "
        "{%0,%1,%2,%3}, {%4,%5,%6,%7}, {%8,%9}, {%0,%1,%2,%3};"
        : "+f"(d[0]), "+f"(d[1]), "+f"(d[2]), "+f"(d[3])
        : "r"(a[0]), "r"(a[1]), "r"(a[2]), "r"(a[3]), "r"(b0), "r"(b1));
}

// ---------------------------------------------------------------------------
// fused fp32 -> fp16 conversion for v / Wv / Wo (one launch, 4-way ILP)
// each block converts 4096 floats (1024 float4)
// ---------------------------------------------------------------------------
struct hf4 { __half a, b, c, d; };

#define V_BLKS  24576     // 32768*3072/4096
#define WV_BLKS 768       // 1024*3072/4096
#define WO_BLKS 256       // 1024*1024/4096
#define SPLIT_BLKS (V_BLKS + WV_BLKS + WO_BLKS)   // 25600

__global__ __launch_bounds__(256)
void split_all_kernel(const float4* __restrict__ v,  __half* __restrict__ vd,
                      const float4* __restrict__ wv, __half* __restrict__ wvd,
                      const float4* __restrict__ wo, __half* __restrict__ wod)
{
    const int g = blockIdx.x;
    const float4* src; __half* dst; size_t local;
    if (g < V_BLKS)                { src = v;  dst = vd;  local = g; }
    else if (g < V_BLKS + WV_BLKS) { src = wv; dst = wvd; local = g - V_BLKS; }
    else                           { src = wo; dst = wod; local = g - V_BLKS - WV_BLKS; }

    const size_t base = local * 1024 + threadIdx.x;
    float4 x[4];
    #pragma unroll
    for (int u = 0; u < 4; u++) x[u] = src[base + u * 256];
    #pragma unroll
    for (int u = 0; u < 4; u++) {
        hf4 H = {__float2half_rn(x[u].x), __float2half_rn(x[u].y),
                 __float2half_rn(x[u].z), __float2half_rn(x[u].w)};
        *(hf4*)(dst + (base + u * 256) * 4) = H;
    }
}

// ============================================================================
// qp partials: part[kc][b][j] = sum_{k in chunk kc} q[b][k] * Wq[j][k]
// ============================================================================
__global__ __launch_bounds__(256)
void qp_part_kernel(const float* __restrict__ q, const float* __restrict__ Wq,
                    float* __restrict__ part)
{
    __shared__ float q_s[64][65];
    __shared__ float w_s[128][65];
    const int t  = threadIdx.x;
    const int jc = blockIdx.x;
    const int kc = blockIdx.y;
    const int k0 = kc * 64;

    #pragma unroll
    for (int p = 0; p < 4; p++) {
        const int f = t + p * 256;
        const int b = f >> 4, c4 = (f & 15) * 4;
        const float4 v = *(const float4*)(q + (size_t)b * 2048 + k0 + c4);
        q_s[b][c4+0] = v.x; q_s[b][c4+1] = v.y; q_s[b][c4+2] = v.z; q_s[b][c4+3] = v.w;
    }
    #pragma unroll
    for (int p = 0; p < 8; p++) {
        const int f = t + p * 256;
        const int j = f >> 4, c4 = (f & 15) * 4;
        const float4 v = *(const float4*)(Wq + (size_t)(jc * 128 + j) * 2048 + k0 + c4);
        w_s[j][c4+0] = v.x; w_s[j][c4+1] = v.y; w_s[j][c4+2] = v.z; w_s[j][c4+3] = v.w;
    }
    __syncthreads();

    const int jj = t & 63;
    const int bg = t >> 6;
    float acc0[16], acc1[16];
    #pragma unroll
    for (int b = 0; b < 16; b++) { acc0[b] = 0.f; acc1[b] = 0.f; }

    #pragma unroll 4
    for (int kk = 0; kk < 64; kk++) {
        const float w0 = w_s[jj][kk];
        const float w1 = w_s[jj + 64][kk];
        #pragma unroll
        for (int b = 0; b < 16; b++) {
            const float qv = q_s[bg * 16 + b][kk];
            acc0[b] = fmaf(qv, w0, acc0[b]);
            acc1[b] = fmaf(qv, w1, acc1[b]);
        }
    }
    #pragma unroll
    for (int b = 0; b < 16; b++) {
        const size_t base = ((size_t)kc * 64 + bg * 16 + b) * DIM + jc * 128;
        part[base + jj]      = acc0[b];
        part[base + jj + 64] = acc1[b];
    }
}

__global__ __launch_bounds__(256)
void qp_reduce_kernel(const float* __restrict__ part, const float* __restrict__ bq,
                      float* __restrict__ qp)
{
    const int b = blockIdx.x;
    const int t = threadIdx.x;
    #pragma unroll
    for (int jj = 0; jj < 4; jj++) {
        const int j = jj * 256 + t;
        float s = 0.f;
        #pragma unroll 8
        for (int kc = 0; kc < 32; kc++)
            s += part[((size_t)kc * 64 + b) * DIM + j];
        qp[(size_t)b * DIM + j] = s + bq[j];
    }
}

// ============================================================================
// w[b][h][c] = sum_d qp[b][h*64+d] * Wq[h*64+d][c];  cbh[b][h] = qp[b,h,:].bq
// ============================================================================
__global__ __launch_bounds__(256)
void wfold_kernel(const float* __restrict__ qp, const float* __restrict__ Wq,
                  const float* __restrict__ bq,
                  float* __restrict__ w, float* __restrict__ cbh)
{
    __shared__ float qp_s[64][65];
    __shared__ float bq_s[64];
    const int t  = threadIdx.x;
    const int h  = blockIdx.x;
    const int cc = blockIdx.y;

    #pragma unroll
    for (int p = 0; p < 4; p++) {
        const int f = t + p * 256;
        const int b = f >> 4, d4 = (f & 15) * 4;
        const float4 v = *(const float4*)(qp + (size_t)b * DIM + h * 64 + d4);
        qp_s[b][d4+0] = v.x; qp_s[b][d4+1] = v.y; qp_s[b][d4+2] = v.z; qp_s[b][d4+3] = v.w;
    }
    if (t < 16) {
        const float4 v = *(const float4*)(bq + h * 64 + t * 4);
        bq_s[t*4+0] = v.x; bq_s[t*4+1] = v.y; bq_s[t*4+2] = v.z; bq_s[t*4+3] = v.w;
    }
    __syncthreads();

    if (cc == 0 && t < 64) {
        float s = 0.f;
        #pragma unroll 8
        for (int d = 0; d < 64; d++) s = fmaf(qp_s[t][d], bq_s[d], s);
        cbh[t * NH + h] = s;
    }

    const int c = cc * 256 + t;
    float acc[64];
    #pragma unroll
    for (int b = 0; b < 64; b++) acc[b] = 0.f;

    for (int d = 0; d < 64; d++) {
        const float wv = Wq[(size_t)(h * 64 + d) * 2048 + c];
        #pragma unroll
        for (int b = 0; b < 64; b++)
            acc[b] = fmaf(qp_s[b][d], wv, acc[b]);
    }
    #pragma unroll
    for (int b = 0; b < 64; b++)
        w[((size_t)b * NH + h) * 2048 + c] = acc[b];
}

// ============================================================================
// scores[b][h][l] = (k[b,l,:] . w[b,h,:] + cbh[b,h]) / 8
// ============================================================================
#define SC_ROW   68
#define SC_KST   (64 * SC_ROW * 4)
#define SC_WST   (16 * SC_ROW * 4)
#define SC_WOFF  (3 * SC_KST)
#define SC_SMEM  (3 * SC_KST + 3 * SC_WST)

__global__ __launch_bounds__(256)
void scores_kernel(const float* __restrict__ k, const float* __restrict__ w,
                   const float* __restrict__ cbh, float* __restrict__ scores)
{
    extern __shared__ __align__(16) char dsm[];
    const int t  = threadIdx.x;
    const int b  = blockIdx.x;
    const int lc = blockIdx.y;
    const uint32_t sbase = smem_u32(dsm);

    auto issue = [&](int c) {
        const int kc = c * 64;
        const uint32_t kb = sbase + (uint32_t)(c % 3) * SC_KST;
        #pragma unroll
        for (int p = 0; p < 4; p++) {
            const int slot = p * 256 + t;
            const int row = slot >> 4, c4 = (slot & 15) * 4;
            cpa16(kb + (row * SC_ROW + c4) * 4,
                  k + ((size_t)(b * 512 + lc * 64 + row)) * 2048 + kc + c4);
        }
        {
            const int row = t >> 4, c4 = (t & 15) * 4;
            cpa16(sbase + SC_WOFF + (uint32_t)(c % 3) * SC_WST + (row * SC_ROW + c4) * 4,
                  w + ((size_t)(b * NH + row)) * 2048 + kc + c4);
        }
        cp_commit();
    };

    issue(0);
    issue(1);

    const int h  = t & 15;
    const int lg = t >> 4;
    float acc[4] = {0.f, 0.f, 0.f, 0.f};

    for (int c = 0; c < 32; c++) {
        if (c + 1 < 32) cp_wait<1>();
        else            cp_wait<0>();
        __syncthreads();
        if (c + 2 < 32) issue(c + 2);

        const float* ks = (const float*)(dsm + (c % 3) * SC_KST);
        const float* ws = (const float*)(dsm + SC_WOFF + (c % 3) * SC_WST);

        #pragma unroll
        for (int kk4 = 0; kk4 < 16; kk4++) {
            const float4 wv = *(const float4*)&ws[h * SC_ROW + kk4 * 4];
            #pragma unroll
            for (int i = 0; i < 4; i++) {
                const float4 kv = *(const float4*)&ks[(lg * 4 + i) * SC_ROW + kk4 * 4];
                acc[i] = fmaf(kv.x, wv.x, acc[i]);
                acc[i] = fmaf(kv.y, wv.y, acc[i]);
                acc[i] = fmaf(kv.z, wv.z, acc[i]);
                acc[i] = fmaf(kv.w, wv.w, acc[i]);
            }
        }
    }

    const float cv = cbh[b * NH + h];
    #pragma unroll
    for (int i = 0; i < 4; i++) {
        const int l = lc * 64 + lg * 4 + i;
        scores[((size_t)b * NH + h) * LEN + l] = (acc[i] + cv) * 0.125f;
    }
}

// ============================================================================
// qe_score -> back gate (sigmoid) + fcw output
// v2: 3-stage cp.async over j-chunks of 64, one sync per chunk.
// thread = (il = t>>2 row, hg = t&3 head group of 4)
// ============================================================================
#define QE_ROW   68                          // 64 + 4 pad (floats)
#define QE_ST    (64 * QE_ROW * 4)           // 17408 B per qe stage
#define QE_SCOFF (3 * QE_ST)                 // 52224
#define QE_SCROW 516                         // 512 + 4 pad (floats)
#define QE_SMEM  (QE_SCOFF + NH * QE_SCROW * 4)   // 52224 + 33024 = 85248

__global__ __launch_bounds__(256)
void qe_kernel(const float* __restrict__ qe,
               const float* __restrict__ cw,
               const float* __restrict__ lambdas,
               const float* __restrict__ scores,
               float* __restrict__ back,
               float* __restrict__ fcw)
{
    extern __shared__ __align__(16) char qsm[];
    float* sc = (float*)(qsm + QE_SCOFF);    // [16][516]

    const int b  = blockIdx.x;
    const int i0 = blockIdx.y * 64;
    const int t  = threadIdx.x;
    const uint32_t sbase = smem_u32(qsm);

    auto issue = [&](int c) {
        const uint32_t qb = sbase + (uint32_t)(c % 3) * QE_ST;
        #pragma unroll
        for (int p = 0; p < 4; p++) {
            const int slot = p * 256 + t;            // 1024 f4 slots
            const int row = slot >> 4, c4 = (slot & 15) * 4;
            cpa16(qb + (row * QE_ROW + c4) * 4,
                  qe + ((size_t)b * LEN + i0 + row) * LEN + c * 64 + c4);
        }
        cp_commit();
    };

    issue(0);
    issue(1);

    // load scores tile [16][512] (2048 f4, 8 per thread)
    #pragma unroll
    for (int p = 0; p < 8; p++) {
        const int f = t + p * 256;
        const int r = f >> 7, c4 = (f & 127) * 4;
        const float4 v = *(const float4*)(scores + (size_t)b * NH * LEN + r * LEN + c4);
        sc[r * QE_SCROW + c4 + 0] = v.x; sc[r * QE_SCROW + c4 + 1] = v.y;
        sc[r * QE_SCROW + c4 + 2] = v.z; sc[r * QE_SCROW + c4 + 3] = v.w;
    }

    const int il = t >> 2;
    const int hg = t & 3;
    float acc[4] = {0.f, 0.f, 0.f, 0.f};

    for (int c = 0; c < 8; c++) {
        if (c + 1 < 8) cp_wait<1>();
        else           cp_wait<0>();
        __syncthreads();            // also covers the sc tile on c==0
        if (c + 2 < 8) issue(c + 2);

        const float* qt = (const float*)(qsm + (c % 3) * QE_ST);
        #pragma unroll 8
        for (int jj = 0; jj < 64; jj++) {
            const float qv = qt[il * QE_ROW + jj];
            const int j = c * 64 + jj;
            acc[0] = fmaf(qv, sc[(hg     ) * QE_SCROW + j], acc[0]);
            acc[1] = fmaf(qv, sc[(hg + 4 ) * QE_SCROW + j], acc[1]);
            acc[2] = fmaf(qv, sc[(hg + 8 ) * QE_SCROW + j], acc[2]);
            acc[3] = fmaf(qv, sc[(hg + 12) * QE_SCROW + j], acc[3]);
        }
    }

    const float c_w = cw[(size_t)b * LEN + i0 + il];
    #pragma unroll
    for (int c = 0; c < 4; c++) {
        const int h = hg + 4 * c;
        const float lam = lambdas[h];
        const float x = acc[c];
        const float z = lam * c_w + (1.f - lam) * x;
        const float bk = 1.f / (1.f + expf(-z));
        back[((size_t)b * NH + h) * LEN + i0 + il] = bk;
        if (h == 0) fcw[(size_t)b * LEN + i0 + il] = x;
    }
}

// ---------------------------------------------------------------------------
// mma.sync fp16 GEMM (R14 config): CTA 128x128, BK=64, 8 warps (4m x 2n),
// 3-stage cp.async, 2 CTA/SM, reg-double-buffered B fragments. Gate in epilogue.
// ---------------------------------------------------------------------------
#define ROW_B    144
#define COMP_B   (128 * ROW_B)           // 18432
#define STAGE_B  (2 * COMP_B)            // 36864
#define GSTAGES  3

template<int OM, bool G>
__global__ __launch_bounds__(256, 2)
void gemm_mma(const __half* __restrict__ Ahi,
              const __half* __restrict__ Bhi,
              const float* __restrict__ bias, const float* __restrict__ gate,
              float* __restrict__ Cf, __half* __restrict__ Chi,
              int M, int N, int K)
{
    extern __shared__ __align__(16) char dsm[];
    const int tid  = threadIdx.x;
    const int wid  = tid >> 5;
    const int lane = tid & 31;
    const int wm = wid & 3;
    const int wn = wid >> 2;
    const int n0 = blockIdx.x * 128;
    const int m0 = blockIdx.y * 128;
    const uint32_t sbase = smem_u32(dsm);

    const __half* aH = Ahi + (size_t)m0 * K;
    const __half* bH = Bhi + (size_t)n0 * K;

    float acc[2][8][4];
    #pragma unroll
    for (int a = 0; a < 2; a++)
        #pragma unroll
        for (int b = 0; b < 8; b++)
            #pragma unroll
            for (int c = 0; c < 4; c++) acc[a][b][c] = 0.f;

    const int NC = K >> 6;

    auto issue = [&](int c) {
        const int kc = c << 6;
        const uint32_t sb = sbase + (uint32_t)(c % GSTAGES) * STAGE_B;
        #pragma unroll
        for (int p = 0; p < 4; p++) {
            const int slot = p * 256 + tid;
            const int row = slot >> 3, sg = (slot & 7) * 8;
            cpa16(sb + row * ROW_B + sg * 2, aH + (size_t)row * K + kc + sg);
        }
        #pragma unroll
        for (int p = 0; p < 4; p++) {
            const int slot = p * 256 + tid;
            const int row = slot >> 3, sg = (slot & 7) * 8;
            cpa16(sb + COMP_B + row * ROW_B + sg * 2, bH + (size_t)row * K + kc + sg);
        }
        cp_commit();
    };

    #pragma unroll
    for (int s = 0; s < GSTAGES - 1; s++) issue(s);

    const int arow = wm * 32 + (lane & 15);
    const int acol = (lane >> 4) * 16;
    const int brow = wn * 64 + ((lane >> 4) << 3) + (lane & 7);
    const int bcol = ((lane >> 3) & 1) * 16;

    for (int c = 0; c < NC; c++) {
        if (c + GSTAGES - 2 < NC) cp_wait<GSTAGES - 2>();
        else                      cp_wait<0>();
        __syncthreads();
        if (c + GSTAGES - 1 < NC) issue(c + GSTAGES - 1);

        const uint32_t sb = sbase + (uint32_t)(c % GSTAGES) * STAGE_B;
        const uint32_t abase = sb + arow * ROW_B + acol;
        const uint32_t bbase = sb + COMP_B + brow * ROW_B + bcol;

        uint32_t Bf[2][4][4];
        #pragma unroll
        for (int bt = 0; bt < 4; bt++)
            ldsm4(Bf[0][bt], bbase + bt * 16 * ROW_B);

        #pragma unroll
        for (int ks = 0; ks < 4; ks++) {
            const uint32_t kb = ks * 32;
            uint32_t Af[2][4];
            #pragma unroll
            for (int mt = 0; mt < 2; mt++)
                ldsm4(Af[mt], abase + mt * 16 * ROW_B + kb);
            if (ks < 3) {
                #pragma unroll
                for (int bt = 0; bt < 4; bt++)
                    ldsm4(Bf[(ks + 1) & 1][bt], bbase + bt * 16 * ROW_B + kb + 32);
            }
            const uint32_t (*Bc)[4] = Bf[ks & 1];
            #pragma unroll
            for (int mt = 0; mt < 2; mt++)
                #pragma unroll
                for (int bt = 0; bt < 4; bt++) {
                    mma_f16(acc[mt][2*bt],   Af[mt], Bc[bt][0], Bc[bt][1]);
                    mma_f16(acc[mt][2*bt+1], Af[mt], Bc[bt][2], Bc[bt][3]);
                }
        }
    }

    // ---- epilogue ----
    const int tg  = lane >> 2;
    const int tc2 = (lane & 3) * 2;
    const int h   = (n0 >> 6) + wn;

    #pragma unroll
    for (int mt = 0; mt < 2; mt++) {
        const int r0 = m0 + wm * 32 + mt * 16 + tg;
        const int r1 = r0 + 8;
        float gv0 = 1.f, gv1 = 1.f;
        if (G) {
            gv0 = gate[(((size_t)(r0 >> 9)) * NH + h) * LEN + (r0 & 511)];
            gv1 = gate[(((size_t)(r1 >> 9)) * NH + h) * LEN + (r1 & 511)];
        }
        #pragma unroll
        for (int nt = 0; nt < 8; nt++) {
            const int cn = n0 + wn * 64 + nt * 8 + tc2;
            const float bs0 = bias[cn], bs1 = bias[cn + 1];
            const float v00 = (acc[mt][nt][0] + bs0) * gv0;
            const float v01 = (acc[mt][nt][1] + bs1) * gv0;
            const float v10 = (acc[mt][nt][2] + bs0) * gv1;
            const float v11 = (acc[mt][nt][3] + bs1) * gv1;
            if (OM == 0) {
                if (r0 < M) *(float2*)&Cf[(size_t)r0 * N + cn] = make_float2(v00, v01);
                if (r1 < M) *(float2*)&Cf[(size_t)r1 * N + cn] = make_float2(v10, v11);
            } else {
                __half2 H0, H1;
                H0.x = __float2half_rn(v00); H0.y = __float2half_rn(v01);
                H1.x = __float2half_rn(v10); H1.y = __float2half_rn(v11);
                if (r0 < M) *(__half2*)(Chi + (size_t)r0 * N + cn) = H0;
                if (r1 < M) *(__half2*)(Chi + (size_t)r1 * N + cn) = H1;
            }
        }
    }
}

// ============================================================================
// launch — R15 structure: splits on side stream ∥ qp chain on main stream,
// join before GEMM2 (gate in GEMM2 epilogue; bit-exact numerics).
// ============================================================================
extern "C" void kernel_launch(void* const* d_in, const int* in_sizes, int n_in,
                              void* d_out, int out_size)
{
    const float* q   = (const float*)d_in[0];
    const float* k   = (const float*)d_in[1];
    const float* v   = (const float*)d_in[2];
    const float* cw  = (const float*)d_in[3];
    const float* qe  = (const float*)d_in[4];
    const float* Wq  = (const float*)d_in[5];
    const float* bq  = (const float*)d_in[6];
    const float* Wv  = (const float*)d_in[7];
    const float* bv  = (const float*)d_in[8];
    const float* Wo  = (const float*)d_in[9];
    const float* bo  = (const float*)d_in[10];
    const float* lam = (const float*)d_in[11];

    float* out_main = (float*)d_out;
    float* out_fcw  = (float*)d_out + OUT_MAIN_ELEMS;

    __half *v_hi, *wv_hi, *wo_hi, *c_hi;
    float *qpp, *qp, *wvec, *cbh, *scores, *back;
    cudaGetSymbolAddress((void**)&v_hi,  g_v_hi);
    cudaGetSymbolAddress((void**)&wv_hi, g_wv_hi);
    cudaGetSymbolAddress((void**)&wo_hi, g_wo_hi);
    cudaGetSymbolAddress((void**)&c_hi,  g_c_hi);
    cudaGetSymbolAddress((void**)&qpp,   g_qp_part);
    cudaGetSymbolAddress((void**)&qp,    g_qp);
    cudaGetSymbolAddress((void**)&wvec,  g_w);
    cudaGetSymbolAddress((void**)&cbh,   g_cbh);
    cudaGetSymbolAddress((void**)&scores, g_scores);
    cudaGetSymbolAddress((void**)&back,   g_back);

    const int smemg = GSTAGES * STAGE_B;   // 110592
    cudaFuncSetAttribute(gemm_mma<1, true>,  cudaFuncAttributeMaxDynamicSharedMemorySize, smemg);
    cudaFuncSetAttribute(gemm_mma<0, false>, cudaFuncAttributeMaxDynamicSharedMemorySize, smemg);
    cudaFuncSetAttribute(scores_kernel, cudaFuncAttributeMaxDynamicSharedMemorySize, SC_SMEM);
    cudaFuncSetAttribute(qe_kernel,     cudaFuncAttributeMaxDynamicSharedMemorySize, QE_SMEM);

    // one-time host resources (no device memory; identical work every call)
    static cudaStream_t s_side = nullptr;
    static cudaEvent_t  e_fork = nullptr, e_join = nullptr;
    if (!s_side) {
        cudaStreamCreateWithFlags(&s_side, cudaStreamNonBlocking);
        cudaEventCreateWithFlags(&e_fork, cudaEventDisableTiming);
        cudaEventCreateWithFlags(&e_join, cudaEventDisableTiming);
    }

    // ---- fork: side stream runs the fused fp16 conversions ----
    cudaEventRecord(e_fork, 0);
    cudaStreamWaitEvent(s_side, e_fork, 0);
    split_all_kernel<<<SPLIT_BLKS, 256, 0, s_side>>>(
        (const float4*)v, v_hi, (const float4*)Wv, wv_hi, (const float4*)Wo, wo_hi);
    cudaEventRecord(e_join, s_side);

    // ---- main stream: exact-fp32 query chain ----
    qp_part_kernel<<<dim3(8, 32), 256>>>(q, Wq, qpp);
    qp_reduce_kernel<<<64, 256>>>(qpp, bq, qp);
    wfold_kernel<<<dim3(16, 8), 256>>>(qp, Wq, bq, wvec, cbh);
    scores_kernel<<<dim3(BSZ, 8), 256, SC_SMEM>>>(k, wvec, cbh, scores);
    qe_kernel<<<dim3(BSZ, 8), 256, QE_SMEM>>>(qe, cw, lam, scores, back, out_fcw);

    // ---- join before GEMM2 (needs v_hi, wv_hi, back) ----
    cudaStreamWaitEvent(0, e_join, 0);

    // GEMM2: v @ Wv^T + bv, gated -> concat (fp16 out)
    gemm_mma<1, true><<<dim3(8, 256), 256, smemg>>>(
        v_hi, wv_hi, bv, back, nullptr, c_hi, M_KV, DIM, 3 * DIM);

    // GEMM3: concat @ Wo^T + bo -> main output (fp32)
    gemm_mma<0, false><<<dim3(8, 256), 256, smemg>>>(
        c_hi, wo_hi, bo, nullptr, out_main, nullptr, M_KV, DIM, DIM);
}